// round 3
// baseline (speedup 1.0000x reference)
#include <cuda_runtime.h>
#include <stdint.h>

#define DIM   300
#define VEC4  (DIM / 4)     // 75 float4 per row
#define VMAX  200000
#define KMAX  16
#define RED_THREADS 256

// Scratch for scores (no cudaMalloc allowed; __device__ global is the sanctioned path)
__device__ float g_scores[VMAX];

// ---------------------------------------------------------------------------
// Kernel 1: scores[r] = dot(embedding[r], embedding[wordid])   (warp per row)
// ---------------------------------------------------------------------------
__global__ __launch_bounds__(256) void dot_kernel(const int* __restrict__ wordid,
                                                  const float* __restrict__ emb,
                                                  int V,
                                                  float* __restrict__ scores)
{
    __shared__ float4 wv[VEC4];
    const int w = *wordid;
    for (int i = threadIdx.x; i < VEC4; i += blockDim.x)
        wv[i] = reinterpret_cast<const float4*>(emb + (size_t)w * DIM)[i];
    __syncthreads();

    const int lane   = threadIdx.x & 31;
    const int warp   = blockIdx.x * (blockDim.x >> 5) + (threadIdx.x >> 5);
    const int nwarps = gridDim.x * (blockDim.x >> 5);

    for (int r = warp; r < V; r += nwarps) {
        const float4* __restrict__ row =
            reinterpret_cast<const float4*>(emb + (size_t)r * DIM);
        float s = 0.f;
        {
            float4 a = row[lane];
            float4 b = wv[lane];
            s += a.x * b.x + a.y * b.y + a.z * b.z + a.w * b.w;
        }
        {
            float4 a = row[lane + 32];
            float4 b = wv[lane + 32];
            s += a.x * b.x + a.y * b.y + a.z * b.z + a.w * b.w;
        }
        if (lane + 64 < VEC4) {
            float4 a = row[lane + 64];
            float4 b = wv[lane + 64];
            s += a.x * b.x + a.y * b.y + a.z * b.z + a.w * b.w;
        }
        #pragma unroll
        for (int off = 16; off; off >>= 1)
            s += __shfl_xor_sync(0xFFFFFFFFu, s, off);
        if (lane == 0)
            scores[r] = s;
    }
}

// ---------------------------------------------------------------------------
// Kernel 2: single-block top-K reduction over scores[0..V)
//   out[0..K)  = top-K values (descending)
//   out[K..2K) = top-K indices (as float), if out_size >= 2K
// Tie-break: lower index first (matches jax.lax.top_k)
// ---------------------------------------------------------------------------
__global__ __launch_bounds__(RED_THREADS) void topk_kernel(const float* __restrict__ scores,
                                                           int V,
                                                           const int* __restrict__ topk_p,
                                                           float* __restrict__ out,
                                                           int out_size)
{
    int K = *topk_p + 1;
    if (K > KMAX) K = KMAX;
    if (K < 1)    K = 1;

    __shared__ float svals[RED_THREADS * KMAX];
    __shared__ int   sids [RED_THREADS * KMAX];

    float lv[KMAX];
    int   li[KMAX];
    #pragma unroll
    for (int i = 0; i < KMAX; i++) { lv[i] = -3.0e38f; li[i] = 0x7FFFFFFF; }
    float kmin = -3.0e38f;

    const int t = threadIdx.x;
    for (int r = t; r < V; r += RED_THREADS) {
        float v = scores[r];
        if (v > kmin) {
            int pos = K - 1;
            while (pos > 0 && lv[pos - 1] < v) {
                lv[pos] = lv[pos - 1];
                li[pos] = li[pos - 1];
                pos--;
            }
            lv[pos] = v;
            li[pos] = r;
            kmin = lv[K - 1];
        }
    }

    for (int i = 0; i < K; i++) {
        svals[t * KMAX + i] = lv[i];
        sids [t * KMAX + i] = li[i];
    }
    __syncthreads();

    if (t == 0) {
        float fv[KMAX];
        int   fi[KMAX];
        #pragma unroll
        for (int i = 0; i < KMAX; i++) { fv[i] = -3.0e38f; fi[i] = 0x7FFFFFFF; }
        float fmin = -3.0e38f;

        for (int tt = 0; tt < RED_THREADS; tt++) {
            for (int kk = 0; kk < K; kk++) {
                float v  = svals[tt * KMAX + kk];
                int   id = sids [tt * KMAX + kk];
                if (id == 0x7FFFFFFF) break;   // this thread's list ended
                bool better = (v > fmin) || (v == fmin && id < fi[K - 1]);
                if (better) {
                    int pos = K - 1;
                    while (pos > 0 &&
                           (fv[pos - 1] < v ||
                            (fv[pos - 1] == v && fi[pos - 1] > id))) {
                        fv[pos] = fv[pos - 1];
                        fi[pos] = fi[pos - 1];
                        pos--;
                    }
                    fv[pos] = v;
                    fi[pos] = id;
                    fmin = fv[K - 1];
                }
            }
        }

        for (int i = 0; i < K && i < out_size; i++)
            out[i] = fv[i];
        if (out_size >= 2 * K) {
            for (int i = 0; i < K; i++)
                out[K + i] = (float)fi[i];
        }
    }
}

// ---------------------------------------------------------------------------
extern "C" void kernel_launch(void* const* d_in, const int* in_sizes, int n_in,
                              void* d_out, int out_size)
{
    const int*   wordid = (const int*)  d_in[0];
    const float* emb    = (const float*)d_in[1];
    const int*   topk   = (const int*)  d_in[2];
    float*       out    = (float*)      d_out;

    const int V = in_sizes[1] / DIM;   // 200000

    static float* scores_dev = nullptr;
    if (!scores_dev)
        cudaGetSymbolAddress((void**)&scores_dev, g_scores);

    dot_kernel<<<1184, 256>>>(wordid, emb, V, scores_dev);
    topk_kernel<<<1, RED_THREADS>>>(scores_dev, V, topk, out, out_size);
}

// round 6
// speedup vs baseline: 1.3404x; 1.3404x over previous
#include <cuda_runtime.h>
#include <stdint.h>

#define DIM   300
#define VEC4  (DIM / 4)     // 75 float4 per row
#define VMAX  200000
#define KMAX  16
#define RED_THREADS 256

// Scratch for scores (no cudaMalloc allowed; __device__ global is the sanctioned path)
__device__ float g_scores[VMAX];

// ---------------------------------------------------------------------------
// Kernel 1: one warp per row, no loop. scores[r] = dot(emb[r], emb[wordid]).
// Query vector held in registers (3 float4 per lane). Row loads are streaming
// (__ldcs) so 240 MB doesn't thrash L2.
// ---------------------------------------------------------------------------
__global__ __launch_bounds__(256) void dot_kernel(const int* __restrict__ wordid,
                                                  const float* __restrict__ emb,
                                                  int V,
                                                  float* __restrict__ scores)
{
    const int lane = threadIdx.x & 31;
    const int r    = blockIdx.x * (blockDim.x >> 5) + (threadIdx.x >> 5);
    if (r >= V) return;

    const int w = __ldg(wordid);
    const float4* __restrict__ wp =
        reinterpret_cast<const float4*>(emb + (size_t)w * DIM);

    // Query vector: same 3 float4 for this lane across the whole grid (L2 hit)
    const float4 b0 = __ldg(wp + lane);
    const float4 b1 = __ldg(wp + lane + 32);
    const bool   t2 = (lane + 64) < VEC4;            // lanes 0..10
    const float4 b2 = t2 ? __ldg(wp + lane + 64) : make_float4(0.f, 0.f, 0.f, 0.f);

    const float4* __restrict__ rp =
        reinterpret_cast<const float4*>(emb + (size_t)r * DIM);

    // 3 independent streaming loads — issued back-to-back, single stall point
    const float4 a0 = __ldcs(rp + lane);
    const float4 a1 = __ldcs(rp + lane + 32);
    const float4 a2 = t2 ? __ldcs(rp + lane + 64) : make_float4(0.f, 0.f, 0.f, 0.f);

    float s = a0.x * b0.x + a0.y * b0.y + a0.z * b0.z + a0.w * b0.w;
    s      += a1.x * b1.x + a1.y * b1.y + a1.z * b1.z + a1.w * b1.w;
    s      += a2.x * b2.x + a2.y * b2.y + a2.z * b2.z + a2.w * b2.w;

    #pragma unroll
    for (int off = 16; off; off >>= 1)
        s += __shfl_xor_sync(0xFFFFFFFFu, s, off);

    if (lane == 0)
        scores[r] = s;
}

// ---------------------------------------------------------------------------
// Kernel 2: single-block top-K reduction over scores[0..V)
//   out[0..K)  = top-K values (descending)
//   out[K..2K) = top-K indices (as float), if out_size >= 2K
// Tie-break: lower index first (matches jax.lax.top_k)
// ---------------------------------------------------------------------------
__global__ __launch_bounds__(RED_THREADS) void topk_kernel(const float* __restrict__ scores,
                                                           int V,
                                                           const int* __restrict__ topk_p,
                                                           float* __restrict__ out,
                                                           int out_size)
{
    int K = *topk_p + 1;
    if (K > KMAX) K = KMAX;
    if (K < 1)    K = 1;

    __shared__ float svals[RED_THREADS * KMAX];
    __shared__ int   sids [RED_THREADS * KMAX];

    float lv[KMAX];
    int   li[KMAX];
    #pragma unroll
    for (int i = 0; i < KMAX; i++) { lv[i] = -3.0e38f; li[i] = 0x7FFFFFFF; }
    float kmin = -3.0e38f;

    const int t = threadIdx.x;
    for (int r = t; r < V; r += RED_THREADS) {
        float v = scores[r];
        if (v > kmin) {
            int pos = K - 1;
            while (pos > 0 && lv[pos - 1] < v) {
                lv[pos] = lv[pos - 1];
                li[pos] = li[pos - 1];
                pos--;
            }
            lv[pos] = v;
            li[pos] = r;
            kmin = lv[K - 1];
        }
    }

    for (int i = 0; i < K; i++) {
        svals[t * KMAX + i] = lv[i];
        sids [t * KMAX + i] = li[i];
    }
    __syncthreads();

    if (t == 0) {
        float fv[KMAX];
        int   fi[KMAX];
        #pragma unroll
        for (int i = 0; i < KMAX; i++) { fv[i] = -3.0e38f; fi[i] = 0x7FFFFFFF; }
        float fmin = -3.0e38f;

        for (int tt = 0; tt < RED_THREADS; tt++) {
            for (int kk = 0; kk < K; kk++) {
                float v  = svals[tt * KMAX + kk];
                int   id = sids [tt * KMAX + kk];
                if (id == 0x7FFFFFFF) break;   // this thread's list ended
                bool better = (v > fmin) || (v == fmin && id < fi[K - 1]);
                if (better) {
                    int pos = K - 1;
                    while (pos > 0 &&
                           (fv[pos - 1] < v ||
                            (fv[pos - 1] == v && fi[pos - 1] > id))) {
                        fv[pos] = fv[pos - 1];
                        fi[pos] = fi[pos - 1];
                        pos--;
                    }
                    fv[pos] = v;
                    fi[pos] = id;
                    fmin = fv[K - 1];
                }
            }
        }

        for (int i = 0; i < K && i < out_size; i++)
            out[i] = fv[i];
        if (out_size >= 2 * K) {
            for (int i = 0; i < K; i++)
                out[K + i] = (float)fi[i];
        }
    }
}

// ---------------------------------------------------------------------------
// No-op pad kernel: steers ncu's "-s 5 -c 1" onto dot_kernel next profile.
// Launch sequence per invocation: [dot, topk, pad, pad, pad]
//   -> global launch index 5 == dot_kernel of the 2nd replay.
// ---------------------------------------------------------------------------
__global__ void pad_kernel() {}

// ---------------------------------------------------------------------------
extern "C" void kernel_launch(void* const* d_in, const int* in_sizes, int n_in,
                              void* d_out, int out_size)
{
    const int*   wordid = (const int*)  d_in[0];
    const float* emb    = (const float*)d_in[1];
    const int*   topk   = (const int*)  d_in[2];
    float*       out    = (float*)      d_out;

    const int V = in_sizes[1] / DIM;   // 200000

    static float* scores_dev = nullptr;
    if (!scores_dev)
        cudaGetSymbolAddress((void**)&scores_dev, g_scores);

    const int warps_per_block = 256 / 32;                      // 8
    const int nblocks = (V + warps_per_block - 1) / warps_per_block;  // 25000

    dot_kernel<<<nblocks, 256>>>(wordid, emb, V, scores_dev);
    topk_kernel<<<1, RED_THREADS>>>(scores_dev, V, topk, out, out_size);

    // profiling steer (cheap; removed once dot_kernel is understood)
    pad_kernel<<<1, 32>>>();
    pad_kernel<<<1, 32>>>();
    pad_kernel<<<1, 32>>>();
}

// round 9
// speedup vs baseline: 1.6953x; 1.2648x over previous
#include <cuda_runtime.h>
#include <stdint.h>

#define DIM       300
#define VEC4      (DIM / 4)          // 75 float4 per row
#define VMAX      200000
#define KMAX      16
#define NBLOCKS   1184
#define NTHREADS  256
#define WPB       (NTHREADS / 32)    // 8 warps per block
#define NWARPS    (NBLOCKS * WPB)    // 9472

// Device-resident staging + scratch (no cudaMalloc allowed; __device__ globals
// are the sanctioned path)
__device__ float    g_emb[(size_t)VMAX * DIM];   // 240 MB staging copy
__device__ float    g_scores[VMAX];
__device__ unsigned g_done = 0;

__device__ __forceinline__ float dot4(float4 a, float4 b)
{
    return a.x * b.x + a.y * b.y + a.z * b.z + a.w * b.w;
}

// ---------------------------------------------------------------------------
// Fused kernel:
//   Phase 1 (all blocks): warp-per-row dot products from g_emb (device-
//                         resident), 2 rows per iteration for MLP=6.
//   Phase 2 (last block): top-K scan of g_scores, write out.
// ---------------------------------------------------------------------------
__global__ __launch_bounds__(NTHREADS) void fused_kernel(const int* __restrict__ wordid,
                                                         const int* __restrict__ topk_p,
                                                         float* __restrict__ out,
                                                         int out_size,
                                                         int V)
{
    const int lane = threadIdx.x & 31;
    const int warp = blockIdx.x * WPB + (threadIdx.x >> 5);

    // ---- query vector in registers (3 float4/lane, L2-hit for all warps) ----
    const int w = __ldg(wordid);
    const float4* __restrict__ wp =
        reinterpret_cast<const float4*>(g_emb + (size_t)w * DIM);
    const float4 zero = make_float4(0.f, 0.f, 0.f, 0.f);
    const bool   t2 = (lane + 64) < VEC4;     // lanes 0..10
    const float4 b0 = __ldg(wp + lane);
    const float4 b1 = __ldg(wp + lane + 32);
    const float4 b2 = t2 ? __ldg(wp + lane + 64) : zero;

    // ---- phase 1: dots, 2 rows per iteration ----
    for (int r = warp; r < V; r += 2 * NWARPS) {
        const int r1   = r + NWARPS;
        const bool has1 = r1 < V;

        const float4* __restrict__ rp0 =
            reinterpret_cast<const float4*>(g_emb + (size_t)r * DIM);
        const float4 a0 = __ldcs(rp0 + lane);
        const float4 a1 = __ldcs(rp0 + lane + 32);
        const float4 a2 = t2 ? __ldcs(rp0 + lane + 64) : zero;

        float4 c0 = zero, c1 = zero, c2 = zero;
        if (has1) {
            const float4* __restrict__ rp1 =
                reinterpret_cast<const float4*>(g_emb + (size_t)r1 * DIM);
            c0 = __ldcs(rp1 + lane);
            c1 = __ldcs(rp1 + lane + 32);
            c2 = t2 ? __ldcs(rp1 + lane + 64) : zero;
        }

        float s0 = dot4(a0, b0) + dot4(a1, b1) + dot4(a2, b2);
        float s1 = dot4(c0, b0) + dot4(c1, b1) + dot4(c2, b2);

        #pragma unroll
        for (int off = 16; off; off >>= 1) {
            s0 += __shfl_xor_sync(0xFFFFFFFFu, s0, off);
            s1 += __shfl_xor_sync(0xFFFFFFFFu, s1, off);
        }
        if (lane == 0) {
            g_scores[r] = s0;
            if (has1) g_scores[r1] = s1;
        }
    }

    // ---- last-block-done handoff ----
    __shared__ bool isLast;
    __threadfence();
    if (threadIdx.x == 0) {
        unsigned prev = atomicAdd(&g_done, 1u);
        isLast = (prev == (unsigned)(gridDim.x - 1));
    }
    __syncthreads();
    if (!isLast) return;
    __threadfence();   // acquire: make all blocks' score stores visible

    // ---- phase 2: top-K over g_scores (256 threads of the last block) ----
    int K = *topk_p + 1;
    if (K > KMAX) K = KMAX;
    if (K < 1)    K = 1;

    __shared__ float svals[NTHREADS * KMAX];
    __shared__ int   sids [NTHREADS * KMAX];

    float lv[KMAX];
    int   li[KMAX];
    #pragma unroll
    for (int i = 0; i < KMAX; i++) { lv[i] = -3.0e38f; li[i] = 0x7FFFFFFF; }
    float kmin = -3.0e38f;

    const int t = threadIdx.x;
    for (int r = t; r < V; r += NTHREADS) {
        float v = g_scores[r];
        if (v > kmin) {
            int pos = K - 1;
            while (pos > 0 && lv[pos - 1] < v) {
                lv[pos] = lv[pos - 1];
                li[pos] = li[pos - 1];
                pos--;
            }
            lv[pos] = v;
            li[pos] = r;
            kmin = lv[K - 1];
        }
    }

    for (int i = 0; i < K; i++) {
        svals[t * KMAX + i] = lv[i];
        sids [t * KMAX + i] = li[i];
    }
    __syncthreads();

    if (t == 0) {
        float fv[KMAX];
        int   fi[KMAX];
        #pragma unroll
        for (int i = 0; i < KMAX; i++) { fv[i] = -3.0e38f; fi[i] = 0x7FFFFFFF; }
        float fmin = -3.0e38f;

        for (int tt = 0; tt < NTHREADS; tt++) {
            for (int kk = 0; kk < K; kk++) {
                float v  = svals[tt * KMAX + kk];
                int   id = sids [tt * KMAX + kk];
                if (id == 0x7FFFFFFF) break;
                bool better = (v > fmin) || (v == fmin && id < fi[K - 1]);
                if (better) {
                    int pos = K - 1;
                    while (pos > 0 &&
                           (fv[pos - 1] < v ||
                            (fv[pos - 1] == v && fi[pos - 1] > id))) {
                        fv[pos] = fv[pos - 1];
                        fi[pos] = fi[pos - 1];
                        pos--;
                    }
                    fv[pos] = v;
                    fi[pos] = id;
                    fmin = fv[K - 1];
                }
            }
        }

        for (int i = 0; i < K && i < out_size; i++)
            out[i] = fv[i];
        if (out_size >= 2 * K) {
            for (int i = 0; i < K; i++)
                out[K + i] = (float)fi[i];
        }

        g_done = 0;   // reset for next (deterministic) replay
    }
}

// ---------------------------------------------------------------------------
extern "C" void kernel_launch(void* const* d_in, const int* in_sizes, int n_in,
                              void* d_out, int out_size)
{
    const int*   wordid = (const int*)  d_in[0];
    const float* emb    = (const float*)d_in[1];
    const int*   topk   = (const int*)  d_in[2];
    float*       out    = (float*)      d_out;

    const int V = in_sizes[1] / DIM;   // 200000

    static float* emb_dev = nullptr;
    if (!emb_dev)
        cudaGetSymbolAddress((void**)&emb_dev, g_emb);

    // Stage the embedding into guaranteed-device memory via the copy engine.
    // If the source is already device DRAM this costs ~70us; if it lives in
    // Grace host memory this runs at the C2C DMA ceiling (~200 GB/s), which
    // is the fastest possible ingest of those bytes anyway.
    cudaMemcpyAsync(emb_dev, emb, (size_t)V * DIM * sizeof(float),
                    cudaMemcpyDefault, 0);

    fused_kernel<<<NBLOCKS, NTHREADS>>>(wordid, topk, out, out_size, V);
}

// round 10
// speedup vs baseline: 2.9513x; 1.7408x over previous
#include <cuda_runtime.h>
#include <stdint.h>

#define DIM       300
#define VEC4      (DIM / 4)          // 75 float4 per row
#define VMAX      200000
#define KMAX      16
#define NBLOCKS   592                // 4 per SM (148 SMs), persistent
#define NTHREADS  256
#define WPB       (NTHREADS / 32)    // 8 warps per block
#define NWARPS    (NBLOCKS * WPB)    // 4736
#define ROWS_PER_ITER 4

// Scratch (no cudaMalloc allowed; __device__ globals are the sanctioned path)
__device__ float    g_scores[VMAX];
__device__ unsigned g_done = 0;

__device__ __forceinline__ float dot4(float4 a, float4 b)
{
    return a.x * b.x + a.y * b.y + a.z * b.z + a.w * b.w;
}

// ---------------------------------------------------------------------------
// Fused kernel, reading the embedding DIRECTLY from its (host-resident) source
// over NVLink-C2C. Plain cached LDG.128 (no __ldcs — streaming hint suspected
// of degrading C2C fetch efficiency), 12 independent loads batched per
// iteration per warp to keep the link saturated (host LDG latency ~1222 cyc).
//   Phase 1 (all blocks): warp computes 4 rows per iteration, grid-stride.
//   Phase 2 (last block): top-K over g_scores, write out.
// ---------------------------------------------------------------------------
__global__ __launch_bounds__(NTHREADS) void fused_kernel(const int* __restrict__ wordid,
                                                         const float* __restrict__ emb,
                                                         const int* __restrict__ topk_p,
                                                         float* __restrict__ out,
                                                         int out_size,
                                                         int V)
{
    const int lane = threadIdx.x & 31;
    const int warp = blockIdx.x * WPB + (threadIdx.x >> 5);

    const float4 zero = make_float4(0.f, 0.f, 0.f, 0.f);
    const bool   t2   = (lane + 64) < VEC4;     // lanes 0..10 do the 3rd load

    // ---- query vector in registers (3 float4/lane; L1-cached host lines) ----
    const int w = __ldg(wordid);
    const float4* __restrict__ wp =
        reinterpret_cast<const float4*>(emb + (size_t)w * DIM);
    const float4 b0 = __ldg(wp + lane);
    const float4 b1 = __ldg(wp + lane + 32);
    const float4 b2 = t2 ? __ldg(wp + lane + 64) : zero;

    // ---- phase 1: 4 rows per iteration, all 12 loads issued before use ----
    for (int base = warp; base < V; base += ROWS_PER_ITER * NWARPS) {
        float4 a[ROWS_PER_ITER][3];
        int    rr[ROWS_PER_ITER];
        bool   hv[ROWS_PER_ITER];

        #pragma unroll
        for (int j = 0; j < ROWS_PER_ITER; j++) {
            rr[j] = base + j * NWARPS;
            hv[j] = rr[j] < V;
            const float4* __restrict__ rp =
                reinterpret_cast<const float4*>(emb + (size_t)rr[j] * DIM);
            // guard address for inactive rows (row 0 is always valid)
            const float4* __restrict__ gp = hv[j] ? rp :
                reinterpret_cast<const float4*>(emb);
            a[j][0] = __ldg(gp + lane);
            a[j][1] = __ldg(gp + lane + 32);
            a[j][2] = t2 ? __ldg(gp + lane + 64) : zero;
        }

        #pragma unroll
        for (int j = 0; j < ROWS_PER_ITER; j++) {
            float s = dot4(a[j][0], b0) + dot4(a[j][1], b1) + dot4(a[j][2], b2);
            #pragma unroll
            for (int off = 16; off; off >>= 1)
                s += __shfl_xor_sync(0xFFFFFFFFu, s, off);
            if (lane == 0 && hv[j])
                g_scores[rr[j]] = s;
        }
    }

    // ---- last-block-done handoff ----
    __shared__ bool isLast;
    __threadfence();
    if (threadIdx.x == 0) {
        unsigned prev = atomicAdd(&g_done, 1u);
        isLast = (prev == (unsigned)(gridDim.x - 1));
    }
    __syncthreads();
    if (!isLast) return;
    __threadfence();   // acquire: all blocks' score stores visible

    // ---- phase 2: top-K over g_scores ----
    int K = *topk_p + 1;
    if (K > KMAX) K = KMAX;
    if (K < 1)    K = 1;

    __shared__ float svals[NTHREADS * KMAX];
    __shared__ int   sids [NTHREADS * KMAX];

    float lv[KMAX];
    int   li[KMAX];
    #pragma unroll
    for (int i = 0; i < KMAX; i++) { lv[i] = -3.0e38f; li[i] = 0x7FFFFFFF; }
    float kmin = -3.0e38f;

    const int t = threadIdx.x;
    for (int r = t; r < V; r += NTHREADS) {
        float v = g_scores[r];
        if (v > kmin) {
            int pos = K - 1;
            while (pos > 0 && lv[pos - 1] < v) {
                lv[pos] = lv[pos - 1];
                li[pos] = li[pos - 1];
                pos--;
            }
            lv[pos] = v;
            li[pos] = r;
            kmin = lv[K - 1];
        }
    }

    for (int i = 0; i < K; i++) {
        svals[t * KMAX + i] = lv[i];
        sids [t * KMAX + i] = li[i];
    }
    __syncthreads();

    if (t == 0) {
        float fv[KMAX];
        int   fi[KMAX];
        #pragma unroll
        for (int i = 0; i < KMAX; i++) { fv[i] = -3.0e38f; fi[i] = 0x7FFFFFFF; }
        float fmin = -3.0e38f;

        for (int tt = 0; tt < NTHREADS; tt++) {
            for (int kk = 0; kk < K; kk++) {
                float v  = svals[tt * KMAX + kk];
                int   id = sids [tt * KMAX + kk];
                if (id == 0x7FFFFFFF) break;
                bool better = (v > fmin) || (v == fmin && id < fi[K - 1]);
                if (better) {
                    int pos = K - 1;
                    while (pos > 0 &&
                           (fv[pos - 1] < v ||
                            (fv[pos - 1] == v && fi[pos - 1] > id))) {
                        fv[pos] = fv[pos - 1];
                        fi[pos] = fi[pos - 1];
                        pos--;
                    }
                    fv[pos] = v;
                    fi[pos] = id;
                    fmin = fv[K - 1];
                }
            }
        }

        for (int i = 0; i < K && i < out_size; i++)
            out[i] = fv[i];
        if (out_size >= 2 * K) {
            for (int i = 0; i < K; i++)
                out[K + i] = (float)fi[i];
        }

        g_done = 0;   // reset for next (deterministic) replay
    }
}

// ---------------------------------------------------------------------------
extern "C" void kernel_launch(void* const* d_in, const int* in_sizes, int n_in,
                              void* d_out, int out_size)
{
    const int*   wordid = (const int*)  d_in[0];
    const float* emb    = (const float*)d_in[1];
    const int*   topk   = (const int*)  d_in[2];
    float*       out    = (float*)      d_out;

    const int V = in_sizes[1] / DIM;   // 200000

    fused_kernel<<<NBLOCKS, NTHREADS>>>(wordid, emb, topk, out, out_size, V);
}